// round 2
// baseline (speedup 1.0000x reference)
#include <cuda_runtime.h>
#include <cuda_bf16.h>
#include <cstdint>

// Problem constants
#define BB 128      // batch
#define TT 256      // timesteps
#define DD 256      // embed dim
#define HH 1024     // hidden
#define CC 10       // classes
#define VV 3        // vocab
#define GRID 128    // persistent CTAs
#define NTHREADS 256
#define HC 8        // h-cols per CTA
#define KSTEPS 128  // 1024 / 8

// SMEM layout (dynamic):
//  [0, 131072)            Bf: float4[2][128][32]  weight fragments (tf32 bits)
//  [131072, +16896)       zsm: float[128][33]
//  [..., +4096)           csm: float[128][8]
//  [..., +384)            xzsm: float[3][32]
#define SMEM_BF_BYTES  (2 * 128 * 32 * 16)
#define SMEM_Z_OFF     SMEM_BF_BYTES
#define SMEM_Z_BYTES   (128 * 33 * 4)
#define SMEM_C_OFF     (SMEM_Z_OFF + SMEM_Z_BYTES)
#define SMEM_C_BYTES   (128 * 8 * 4)
#define SMEM_XZ_OFF    (SMEM_C_OFF + SMEM_C_BYTES)
#define SMEM_XZ_BYTES  (3 * 32 * 4)
#define SMEM_TOTAL     (SMEM_XZ_OFF + SMEM_XZ_BYTES)

// Global scratch (no cudaMalloc allowed)
__device__ __align__(16) float g_h[2][BB * HH];     // ping-pong hidden state
__device__ __align__(16) float g_xz3[VV * 4 * HH];  // per-token x-side projection
__device__ int      g_xidx[TT * BB];                // token index, time-major
__device__ int      g_x64;                          // 1 if x is int64, 0 if int32
__device__ unsigned g_bar_count;
__device__ unsigned g_bar_gen;

// ---------------------------------------------------------------------------
__device__ __forceinline__ unsigned f2tf32(float f) {
    unsigned r;
    asm("cvt.rna.tf32.f32 %0, %1;" : "=r"(r) : "f"(f));
    return r;
}

__device__ __forceinline__ void mma_tf32(float& c0, float& c1, float& c2, float& c3,
                                         unsigned a0, unsigned a1, unsigned a2, unsigned a3,
                                         unsigned b0, unsigned b1) {
    asm volatile(
        "mma.sync.aligned.m16n8k8.row.col.f32.tf32.tf32.f32 "
        "{%0,%1,%2,%3}, {%4,%5,%6,%7}, {%8,%9}, {%0,%1,%2,%3};"
        : "+f"(c0), "+f"(c1), "+f"(c2), "+f"(c3)
        : "r"(a0), "r"(a1), "r"(a2), "r"(a3), "r"(b0), "r"(b1));
}

__device__ __forceinline__ void grid_barrier(unsigned target) {
    __threadfence();
    __syncthreads();
    if (threadIdx.x == 0) {
        unsigned old = atomicAdd(&g_bar_count, 1u);
        if (old == GRID - 1) {
            atomicExch(&g_bar_count, 0u);
            __threadfence();
            atomicAdd(&g_bar_gen, 1u);
        } else {
            while (*((volatile unsigned*)&g_bar_gen) < target) {}
        }
    }
    __syncthreads();
}

__device__ __forceinline__ float sigmf(float x) { return 1.0f / (1.0f + expf(-x)); }

// ---------------------------------------------------------------------------
// Reset barrier state each replay (graph determinism)
__global__ void k_init() {
    g_bar_count = 0u;
    g_bar_gen = 0u;
}

// Detect x dtype WITHOUT reading past the int32-sized allocation.
// Tokens are in [0,3). If int64: every hi word of the first 2048 pairs is 0.
// If int32: odd words are random tokens, all-zero with prob 3^-2048 ~ 0.
__global__ void k_detect(const unsigned* __restrict__ xw) {
    __shared__ int flag;
    if (threadIdx.x == 0) flag = 0;
    __syncthreads();
    for (int i = threadIdx.x; i < 2048; i += blockDim.x)
        if (xw[2 * i + 1] != 0u) flag = 1;
    __syncthreads();
    if (threadIdx.x == 0) g_x64 = (flag == 0) ? 1 : 0;
}

// xidx[t*B + b] = x[b*T + t], dtype-safe
__global__ void k_idx(const void* __restrict__ x) {
    int b = blockIdx.x;      // [0,128)
    int t = threadIdx.x;     // [0,256)
    long long v;
    if (g_x64) v = ((const long long*)x)[(size_t)b * TT + t];
    else       v = ((const int*)x)[(size_t)b * TT + t];
    g_xidx[t * BB + b] = (int)v;
}

// xz3[v][gate*1024 + j] = b_gate[j] + sum_d emb[v,d] * W_gate_x[d,j]
__global__ void k_xz3(const float* __restrict__ emb,
                      const float* __restrict__ W_gx, const float* __restrict__ W_ix,
                      const float* __restrict__ W_fx, const float* __restrict__ W_ox,
                      const float* __restrict__ b_g, const float* __restrict__ b_i,
                      const float* __restrict__ b_f, const float* __restrict__ b_o) {
    int gid = blockIdx.x * blockDim.x + threadIdx.x;  // [0, 3*4096)
    if (gid >= VV * 4 * HH) return;
    int v = gid >> 12;
    int col = gid & 4095;
    int gate = col >> 10;
    int j = col & 1023;
    const float* W = (gate == 0) ? W_gx : (gate == 1) ? W_ix : (gate == 2) ? W_fx : W_ox;
    const float* bb = (gate == 0) ? b_g : (gate == 1) ? b_i : (gate == 2) ? b_f : b_o;
    float s = bb[j];
    const float* ev = emb + v * DD;
#pragma unroll 8
    for (int d = 0; d < DD; ++d) s += ev[d] * W[d * HH + j];
    g_xz3[gid] = s;
}

// ---------------------------------------------------------------------------
// Persistent recurrent kernel.
// CTA ng owns h-cols [8*ng, 8*ng+8); z-cols lc in [0,32): lc = gate*8 + j.
// Warp w computes rows [16w, 16w+16) x all 32 z-cols (4 mma n-tiles == 4 gates).
__global__ void __launch_bounds__(NTHREADS, 1)
lstm_persistent(const float* __restrict__ W_gh, const float* __restrict__ W_ih,
                const float* __restrict__ W_fh, const float* __restrict__ W_oh) {
    extern __shared__ __align__(16) char smem[];
    float4* Bf = (float4*)smem;                       // [2][128][32] fragment-ordered tf32
    float* zsm = (float*)(smem + SMEM_Z_OFF);         // [128][33]
    float* csm = (float*)(smem + SMEM_C_OFF);         // [128][8]
    float* xzsm = (float*)(smem + SMEM_XZ_OFF);       // [3][32]

    const int ng = blockIdx.x;
    const int tid = threadIdx.x;
    const int w = tid >> 5;
    const int lane = tid & 31;

    // ---- One-time: weight slice -> fragment-ordered SMEM (tf32, rna-rounded) ----
    // For ntile nt (== gate), lane t: b0 = Wh[8ks + t%4][lc], b1 = Wh[8ks+4 + t%4][lc],
    // lc = 8*nt + t/4.  float4 packs (b0,b1) of ntiles (2p, 2p+1).
    for (int i = 0; i < 32; ++i) {
        int e = tid + NTHREADS * i;      // [0, 8192)
        int t = e & 31;
        int ks = (e >> 5) & 127;
        int p = e >> 12;                 // {0,1}
        int k0 = 8 * ks + (t & 3);
        int lcA = 16 * p + (t >> 2);     // ntile 2p
        int lcB = lcA + 8;               // ntile 2p+1
        int gA = lcA >> 3, jA = lcA & 7;
        int gB = lcB >> 3, jB = lcB & 7;
        const float* WA = (gA == 0) ? W_gh : (gA == 1) ? W_ih : (gA == 2) ? W_fh : W_oh;
        const float* WB = (gB == 0) ? W_gh : (gB == 1) ? W_ih : (gB == 2) ? W_fh : W_oh;
        int colA = ng * HC + jA;
        int colB = ng * HC + jB;
        float4 v;
        v.x = __uint_as_float(f2tf32(WA[(size_t)k0 * HH + colA]));
        v.y = __uint_as_float(f2tf32(WA[(size_t)(k0 + 4) * HH + colA]));
        v.z = __uint_as_float(f2tf32(WB[(size_t)k0 * HH + colB]));
        v.w = __uint_as_float(f2tf32(WB[(size_t)(k0 + 4) * HH + colB]));
        Bf[e] = v;
    }

    // xz slice for this CTA: [3][32]
    if (tid < VV * 32) {
        int v = tid >> 5;
        int lc = tid & 31;
        xzsm[tid] = g_xz3[v * 4096 + (lc >> 3) * HH + ng * HC + (lc & 7)];
    }

    // c = 0, h(buf0) = 0 for our slice
#pragma unroll
    for (int i = 0; i < 4; ++i) {
        int e = tid + NTHREADS * i;      // [0,1024)
        csm[e] = 0.0f;
        int row = e >> 3;
        int j = e & 7;
        __stcg(&g_h[0][row * HH + ng * HC + j], 0.0f);
    }

    unsigned tg = 0;
    grid_barrier(++tg);

    // ---- Recurrence ----
    const int row0 = 16 * w + (lane >> 2);
    const int q = lane & 3;
    const int crow = 16 * w + (lane >> 2);
    const int ccol = (lane & 3) * 2;
    const int grow = tid >> 1;
    const int hj0 = (tid & 1) * 4;

    for (int t = 0; t < TT; ++t) {
        const float* hin = g_h[t & 1];
        float* hout = g_h[(t + 1) & 1];

        float acc[4][4];
#pragma unroll
        for (int nt = 0; nt < 4; ++nt)
#pragma unroll
            for (int r = 0; r < 4; ++r) acc[nt][r] = 0.0f;

        const float* pa0 = hin + row0 * HH + q;
        const float* pa1 = pa0 + 8 * HH;
        const float4* bfp = ((const float4*)smem) + lane;

#pragma unroll 8
        for (int ks = 0; ks < KSTEPS; ++ks) {
            unsigned a0 = f2tf32(__ldcg(pa0 + 8 * ks));
            unsigned a2 = f2tf32(__ldcg(pa0 + 8 * ks + 4));
            unsigned a1 = f2tf32(__ldcg(pa1 + 8 * ks));
            unsigned a3 = f2tf32(__ldcg(pa1 + 8 * ks + 4));
            float4 b01 = bfp[ks * 32];
            float4 b23 = bfp[(128 + ks) * 32];
            mma_tf32(acc[0][0], acc[0][1], acc[0][2], acc[0][3], a0, a1, a2, a3,
                     __float_as_uint(b01.x), __float_as_uint(b01.y));
            mma_tf32(acc[1][0], acc[1][1], acc[1][2], acc[1][3], a0, a1, a2, a3,
                     __float_as_uint(b01.z), __float_as_uint(b01.w));
            mma_tf32(acc[2][0], acc[2][1], acc[2][2], acc[2][3], a0, a1, a2, a3,
                     __float_as_uint(b23.x), __float_as_uint(b23.y));
            mma_tf32(acc[3][0], acc[3][1], acc[3][2], acc[3][3], a0, a1, a2, a3,
                     __float_as_uint(b23.z), __float_as_uint(b23.w));
        }

        // z tile -> SMEM (rows x 32 z-cols)
#pragma unroll
        for (int nt = 0; nt < 4; ++nt) {
            zsm[crow * 33 + nt * 8 + ccol]           = acc[nt][0];
            zsm[crow * 33 + nt * 8 + ccol + 1]       = acc[nt][1];
            zsm[(crow + 8) * 33 + nt * 8 + ccol]     = acc[nt][2];
            zsm[(crow + 8) * 33 + nt * 8 + ccol + 1] = acc[nt][3];
        }
        __syncthreads();

        // Gate math: thread handles (row = tid/2, hj = hj0..hj0+3)
        {
            int v = g_xidx[t * BB + grow];
            const float* xzv = xzsm + v * 32;
            float hv[4];
#pragma unroll
            for (int jj = 0; jj < 4; ++jj) {
                int hj = hj0 + jj;
                float zg = zsm[grow * 33 + hj]      + xzv[hj];
                float zi = zsm[grow * 33 + 8 + hj]  + xzv[8 + hj];
                float zf = zsm[grow * 33 + 16 + hj] + xzv[16 + hj];
                float zo = zsm[grow * 33 + 24 + hj] + xzv[24 + hj];
                float gg = tanhf(zg);
                float ii = sigmf(zi);
                float ff = sigmf(zf);
                float oo = sigmf(zo);
                float c = csm[grow * 8 + hj] * ff + gg * ii;
                csm[grow * 8 + hj] = c;
                hv[jj] = tanhf(c) * oo;
            }
            float4 hvec = make_float4(hv[0], hv[1], hv[2], hv[3]);
            __stcg((float4*)(hout + grow * HH + ng * HC + hj0), hvec);
        }

        grid_barrier(++tg);
    }
}

// ---------------------------------------------------------------------------
// Final projection + log_softmax. h_final lives in g_h[0] (T=256 is even).
__global__ void k_final(const float* __restrict__ W_ph, const float* __restrict__ b_p,
                        float* __restrict__ out) {
    __shared__ float part[CC][128];
    __shared__ float lg[CC];
    __shared__ float red[2];
    int b = blockIdx.x;
    int tid = threadIdx.x;
    const float* hrow = g_h[0] + b * HH;
    float loc[CC];
#pragma unroll
    for (int c = 0; c < CC; ++c) loc[c] = 0.0f;
    for (int k = tid; k < HH; k += 128) {
        float hv = hrow[k];
#pragma unroll
        for (int c = 0; c < CC; ++c) loc[c] += hv * W_ph[k * CC + c];
    }
#pragma unroll
    for (int c = 0; c < CC; ++c) part[c][tid] = loc[c];
    __syncthreads();
    if (tid < CC) {
        float s = 0.0f;
        for (int k = 0; k < 128; ++k) s += part[tid][k];
        lg[tid] = s + b_p[tid];
    }
    __syncthreads();
    if (tid == 0) {
        float m = -1e30f;
        for (int c = 0; c < CC; ++c) m = fmaxf(m, lg[c]);
        float s = 0.0f;
        for (int c = 0; c < CC; ++c) s += expf(lg[c] - m);
        red[0] = m;
        red[1] = logf(s);
    }
    __syncthreads();
    if (tid < CC) out[b * CC + tid] = lg[tid] - red[0] - red[1];
}

// ---------------------------------------------------------------------------
extern "C" void kernel_launch(void* const* d_in, const int* in_sizes, int n_in,
                              void* d_out, int out_size) {
    const void* x        = d_in[0];
    const float* emb     = (const float*)d_in[1];
    const float* W_gx    = (const float*)d_in[2];
    const float* W_ix    = (const float*)d_in[3];
    const float* W_fx    = (const float*)d_in[4];
    const float* W_ox    = (const float*)d_in[5];
    const float* W_gh    = (const float*)d_in[6];
    const float* W_ih    = (const float*)d_in[7];
    const float* W_fh    = (const float*)d_in[8];
    const float* W_oh    = (const float*)d_in[9];
    const float* b_g     = (const float*)d_in[10];
    const float* b_i     = (const float*)d_in[11];
    const float* b_f     = (const float*)d_in[12];
    const float* b_o     = (const float*)d_in[13];
    const float* W_ph    = (const float*)d_in[14];
    const float* b_p     = (const float*)d_in[15];
    float* out = (float*)d_out;

    cudaFuncSetAttribute(lstm_persistent, cudaFuncAttributeMaxDynamicSharedMemorySize,
                         SMEM_TOTAL);

    k_init<<<1, 1>>>();
    k_detect<<<1, 256>>>((const unsigned*)x);
    k_idx<<<BB, TT>>>(x);
    k_xz3<<<(VV * 4 * HH + 255) / 256, 256>>>(emb, W_gx, W_ix, W_fx, W_ox, b_g, b_i, b_f, b_o);
    lstm_persistent<<<GRID, NTHREADS, SMEM_TOTAL>>>(W_gh, W_ih, W_fh, W_oh);
    k_final<<<BB, 128>>>(W_ph, b_p, out);
}

// round 3
// speedup vs baseline: 3.9628x; 3.9628x over previous
#include <cuda_runtime.h>
#include <cuda_fp16.h>
#include <cstdint>

// Problem constants
#define BB 128      // batch
#define TT 256      // timesteps
#define DD 256      // embed dim
#define HH 1024     // hidden
#define CC 10       // classes
#define VV 3        // vocab
#define GRID 128    // persistent CTAs (1 per 8 h-cols)
#define NTHREADS 256
#define KS16 64     // 1024 / 16 (K per m16n8k16 mma)

// SMEM: Bf uint4[2][64][32] = 64KB weight fragments (fp16), then xzsm[3][33]
#define SMEM_BF_BYTES (2 * 64 * 32 * 16)
#define SMEM_XZ_OFF   SMEM_BF_BYTES
#define SMEM_TOTAL    (SMEM_XZ_OFF + 3 * 33 * 4)

// h in A-fragment order, fp16: [buf][ns2(8-col slice)][warp-row-group][lane]
// uint2 = { half2(h[R][c], h[R][c+1]), half2(h[R+8][c], h[R+8][c+1]) }
// with R = 16*wg + lane/4, c = 8*ns2 + 2*(lane%4)
__device__ uint2 g_hfrag[2][128][8][32];
__device__ float g_xz3[VV * 4 * HH];   // per-token x-side projection [v][gate*1024+j]
__device__ int   g_xidx[TT * BB];      // token index, time-major
__device__ int   g_x64;
__device__ volatile unsigned g_flag[GRID];
__device__ volatile unsigned g_gen;

// ---------------------------------------------------------------------------
__device__ __forceinline__ unsigned packh2(float a, float b) {
    __half2 h = __floats2half2_rn(a, b);
    return *(unsigned*)&h;
}

__device__ __forceinline__ uint2 ldcg2(const uint2* p) {
    uint2 r;
    asm volatile("ld.global.cg.v2.u32 {%0,%1},[%2];" : "=r"(r.x), "=r"(r.y) : "l"(p));
    return r;
}

__device__ __forceinline__ void mma_f16(float* c, unsigned a0, unsigned a1,
                                        unsigned a2, unsigned a3,
                                        unsigned b0, unsigned b1) {
    asm volatile(
        "mma.sync.aligned.m16n8k16.row.col.f32.f16.f16.f32 "
        "{%0,%1,%2,%3}, {%4,%5,%6,%7}, {%8,%9}, {%0,%1,%2,%3};"
        : "+f"(c[0]), "+f"(c[1]), "+f"(c[2]), "+f"(c[3])
        : "r"(a0), "r"(a1), "r"(a2), "r"(a3), "r"(b0), "r"(b1));
}

__device__ __forceinline__ float sigmf(float x) { return 1.0f / (1.0f + __expf(-x)); }

__device__ __forceinline__ float lstm_elem(float zg, float zi, float zf, float zo, float& c) {
    float gg = tanhf(zg);
    float ii = sigmf(zi);
    float ff = sigmf(zf);
    float oo = sigmf(zo);
    c = c * ff + gg * ii;
    return tanhf(c) * oo;
}

// Grid barrier: per-CTA flag stores, CTA0 aggregates, broadcast gen.
__device__ __forceinline__ void gbar(unsigned tgt, int ng, int tid) {
    __threadfence();
    __syncthreads();
    if (ng == 0) {
        if (tid == 0) g_flag[0] = tgt;
        if (tid < GRID) { while (g_flag[tid] < tgt) {} }
        __syncthreads();
        if (tid == 0) g_gen = tgt;
        __syncthreads();
    } else {
        if (tid == 0) {
            g_flag[ng] = tgt;
            while (g_gen < tgt) {}
        }
        __syncthreads();
    }
}

// ---------------------------------------------------------------------------
__global__ void k_init() {
    int tid = threadIdx.x;
    if (tid < GRID) g_flag[tid] = 0u;
    if (tid == 0) g_gen = 0u;
}

// Detect x dtype without reading past an int32-sized allocation.
__global__ void k_detect(const unsigned* __restrict__ xw) {
    __shared__ int flag;
    if (threadIdx.x == 0) flag = 0;
    __syncthreads();
    for (int i = threadIdx.x; i < 2048; i += blockDim.x)
        if (xw[2 * i + 1] != 0u) flag = 1;
    __syncthreads();
    if (threadIdx.x == 0) g_x64 = (flag == 0) ? 1 : 0;
}

__global__ void k_idx(const void* __restrict__ x) {
    int b = blockIdx.x;
    int t = threadIdx.x;
    long long v;
    if (g_x64) v = ((const long long*)x)[(size_t)b * TT + t];
    else       v = ((const int*)x)[(size_t)b * TT + t];
    g_xidx[t * BB + b] = (int)v;
}

__global__ void k_xz3(const float* __restrict__ emb,
                      const float* __restrict__ W_gx, const float* __restrict__ W_ix,
                      const float* __restrict__ W_fx, const float* __restrict__ W_ox,
                      const float* __restrict__ b_g, const float* __restrict__ b_i,
                      const float* __restrict__ b_f, const float* __restrict__ b_o) {
    int gid = blockIdx.x * blockDim.x + threadIdx.x;
    if (gid >= VV * 4 * HH) return;
    int v = gid >> 12;
    int col = gid & 4095;
    int gate = col >> 10;
    int j = col & 1023;
    const float* W = (gate == 0) ? W_gx : (gate == 1) ? W_ix : (gate == 2) ? W_fx : W_ox;
    const float* bb = (gate == 0) ? b_g : (gate == 1) ? b_i : (gate == 2) ? b_f : b_o;
    float s = bb[j];
    const float* ev = emb + v * DD;
#pragma unroll 8
    for (int d = 0; d < DD; ++d) s += ev[d] * W[d * HH + j];
    g_xz3[gid] = s;
}

// ---------------------------------------------------------------------------
// Persistent recurrent kernel. CTA ng owns h-cols [8ng, 8ng+8).
// Warp wg: batch rows [16wg, 16wg+16), all 32 z-cols (ntile = gate).
// c-state in registers; z never leaves the mma accumulators.
__global__ void __launch_bounds__(NTHREADS, 1)
lstm_persistent(const float* __restrict__ W_gh, const float* __restrict__ W_ih,
                const float* __restrict__ W_fh, const float* __restrict__ W_oh) {
    extern __shared__ __align__(16) char smem[];
    uint4* Bf = (uint4*)smem;                     // [2][64][32]
    float* xzsm = (float*)(smem + SMEM_XZ_OFF);   // [3][33]

    const int ng = blockIdx.x;
    const int tid = threadIdx.x;
    const int wg = tid >> 5;
    const int lane = tid & 31;
    const int q = lane & 3;
    const int r4 = lane >> 2;
    const int R = 16 * wg + r4;

    // ---- One-time: weight slice -> fp16 B-fragments in SMEM ----
    // Bf[p][ks][t]: .x/.y = b0/b1 of ntile 2p, .z/.w = ntile 2p+1
    // b0 = half2(W[16ks+2q][col], W[16ks+2q+1][col]), b1 = rows +8; col = 8ng + t/4
    for (int i = tid; i < 2 * KS16 * 32; i += NTHREADS) {
        int t = i & 31;
        int ks = (i >> 5) & 63;
        int p = i >> 11;                      // 0: gates g,i  1: gates f,o
        int col = ng * 8 + (t >> 2);
        int k0 = 16 * ks + 2 * (t & 3);
        const float* WA = p ? W_fh : W_gh;
        const float* WB = p ? W_oh : W_ih;
        uint4 v;
        v.x = packh2(WA[(size_t)k0 * HH + col],       WA[(size_t)(k0 + 1) * HH + col]);
        v.y = packh2(WA[(size_t)(k0 + 8) * HH + col], WA[(size_t)(k0 + 9) * HH + col]);
        v.z = packh2(WB[(size_t)k0 * HH + col],       WB[(size_t)(k0 + 1) * HH + col]);
        v.w = packh2(WB[(size_t)(k0 + 8) * HH + col], WB[(size_t)(k0 + 9) * HH + col]);
        Bf[i] = v;
    }

    // xz slice: xzsm[v][gate*8 + j] for this CTA's 8 cols (stride 33 vs bank conflicts)
    for (int i = tid; i < VV * 32; i += NTHREADS) {
        int v = i >> 5;
        int lc = i & 31;
        xzsm[v * 33 + lc] = g_xz3[v * 4096 + (lc >> 3) * HH + ng * 8 + (lc & 7)];
    }

    // h(buf0) = 0 for our slice
    {
        uint2 z; z.x = 0u; z.y = 0u;
        g_hfrag[0][ng][tid >> 5][tid & 31] = z;
    }

    unsigned tg = 1;
    gbar(tg, ng, tid);

    float c0 = 0.0f, c1 = 0.0f, c2 = 0.0f, c3 = 0.0f;

    for (int t = 0; t < TT; ++t) {
        const uint2* hb = &g_hfrag[t & 1][0][wg][lane];   // slice stride = 256 uint2
        const uint4* bf0 = Bf + lane;
        const uint4* bf1 = Bf + 2048 + lane;

        float acc[4][4];
#pragma unroll
        for (int g = 0; g < 4; ++g)
#pragma unroll
            for (int e = 0; e < 4; ++e) acc[g][e] = 0.0f;

#pragma unroll 8
        for (int ks = 0; ks < KS16; ++ks) {
            uint2 A01 = ldcg2(hb + (2 * ks) * 256);       // cols 16ks+2q, +1 (rows R, R+8)
            uint2 A23 = ldcg2(hb + (2 * ks + 1) * 256);   // cols 16ks+8+2q, +9
            uint4 B01 = bf0[ks * 32];
            uint4 B23 = bf1[ks * 32];
            mma_f16(acc[0], A01.x, A01.y, A23.x, A23.y, B01.x, B01.y);
            mma_f16(acc[1], A01.x, A01.y, A23.x, A23.y, B01.z, B01.w);
            mma_f16(acc[2], A01.x, A01.y, A23.x, A23.y, B23.x, B23.y);
            mma_f16(acc[3], A01.x, A01.y, A23.x, A23.y, B23.z, B23.w);
        }

        // Gate math entirely in registers (C-fragment == gate-math element set)
        int vA = __ldg(&g_xidx[t * BB + R]);
        int vB = __ldg(&g_xidx[t * BB + R + 8]);
        const float* xA = xzsm + vA * 33 + 2 * q;   // xA[g*8 + e] = xz[gate g][col 2q+e]
        const float* xB = xzsm + vB * 33 + 2 * q;

        float h0 = lstm_elem(acc[0][0] + xA[0], acc[1][0] + xA[8],
                             acc[2][0] + xA[16], acc[3][0] + xA[24], c0);
        float h1 = lstm_elem(acc[0][1] + xA[1], acc[1][1] + xA[9],
                             acc[2][1] + xA[17], acc[3][1] + xA[25], c1);
        float h2 = lstm_elem(acc[0][2] + xB[0], acc[1][2] + xB[8],
                             acc[2][2] + xB[16], acc[3][2] + xB[24], c2);
        float h3 = lstm_elem(acc[0][3] + xB[1], acc[1][3] + xB[9],
                             acc[2][3] + xB[17], acc[3][3] + xB[25], c3);

        uint2 out;
        out.x = packh2(h0, h1);   // (R, 2q), (R, 2q+1)
        out.y = packh2(h2, h3);   // (R+8, 2q), (R+8, 2q+1)
        g_hfrag[(t + 1) & 1][ng][wg][lane] = out;

        gbar(++tg, ng, tid);
    }
}

// ---------------------------------------------------------------------------
// Final projection + log_softmax; decodes fragment layout. h_final in buf 0.
__global__ void k_final(const float* __restrict__ W_ph, const float* __restrict__ b_p,
                        float* __restrict__ out) {
    __shared__ float part[CC][128];
    __shared__ float lg[CC];
    __shared__ float red[2];
    int b = blockIdx.x;
    int tid = threadIdx.x;
    int wg = b >> 4;
    int rr = b & 7;
    int e1 = (b >> 3) & 1;

    float loc[CC];
#pragma unroll
    for (int c = 0; c < CC; ++c) loc[c] = 0.0f;
    for (int col = tid; col < HH; col += 128) {
        int ns2 = col >> 3;
        int q = (col & 7) >> 1;
        int e0 = col & 1;
        uint2 ent = g_hfrag[0][ns2][wg][rr * 4 + q];
        unsigned word = e1 ? ent.y : ent.x;
        __half2 hh = *(__half2*)&word;
        float hv = e0 ? __high2float(hh) : __low2float(hh);
#pragma unroll
        for (int c = 0; c < CC; ++c) loc[c] += hv * W_ph[col * CC + c];
    }
#pragma unroll
    for (int c = 0; c < CC; ++c) part[c][tid] = loc[c];
    __syncthreads();
    if (tid < CC) {
        float s = 0.0f;
        for (int k = 0; k < 128; ++k) s += part[tid][k];
        lg[tid] = s + b_p[tid];
    }
    __syncthreads();
    if (tid == 0) {
        float m = -1e30f;
        for (int c = 0; c < CC; ++c) m = fmaxf(m, lg[c]);
        float s = 0.0f;
        for (int c = 0; c < CC; ++c) s += expf(lg[c] - m);
        red[0] = m;
        red[1] = logf(s);
    }
    __syncthreads();
    if (tid < CC) out[b * CC + tid] = lg[tid] - red[0] - red[1];
}

// ---------------------------------------------------------------------------
extern "C" void kernel_launch(void* const* d_in, const int* in_sizes, int n_in,
                              void* d_out, int out_size) {
    const void* x        = d_in[0];
    const float* emb     = (const float*)d_in[1];
    const float* W_gx    = (const float*)d_in[2];
    const float* W_ix    = (const float*)d_in[3];
    const float* W_fx    = (const float*)d_in[4];
    const float* W_ox    = (const float*)d_in[5];
    const float* W_gh    = (const float*)d_in[6];
    const float* W_ih    = (const float*)d_in[7];
    const float* W_fh    = (const float*)d_in[8];
    const float* W_oh    = (const float*)d_in[9];
    const float* b_g     = (const float*)d_in[10];
    const float* b_i     = (const float*)d_in[11];
    const float* b_f     = (const float*)d_in[12];
    const float* b_o     = (const float*)d_in[13];
    const float* W_ph    = (const float*)d_in[14];
    const float* b_p     = (const float*)d_in[15];
    float* out = (float*)d_out;

    cudaFuncSetAttribute(lstm_persistent, cudaFuncAttributeMaxDynamicSharedMemorySize,
                         SMEM_TOTAL);

    k_init<<<1, 128>>>();
    k_detect<<<1, 256>>>((const unsigned*)x);
    k_idx<<<BB, TT>>>(x);
    k_xz3<<<(VV * 4 * HH + 255) / 256, 256>>>(emb, W_gx, W_ix, W_fx, W_ox, b_g, b_i, b_f, b_o);
    lstm_persistent<<<GRID, NTHREADS, SMEM_TOTAL>>>(W_gh, W_ih, W_fh, W_oh);
    k_final<<<BB, 128>>>(W_ph, b_p, out);
}

// round 4
// speedup vs baseline: 4.2505x; 1.0726x over previous
#include <cuda_runtime.h>
#include <cuda_fp16.h>
#include <cstdint>

// Problem constants
#define BB 128      // batch
#define TT 256      // timesteps
#define DD 256      // embed dim
#define HH 1024     // hidden
#define CC 10       // classes
#define VV 3        // vocab
#define GRID 128    // persistent CTAs (1 per 8 h-cols)
#define NTHREADS 256
#define KS16 64     // 1024 / 16 (K per m16n8k16 mma)

// SMEM: Bf uint4[2][64][32] = 64KB weight fragments (fp16), then xzsm[3][33]
#define SMEM_BF_BYTES (2 * 64 * 32 * 16)
#define SMEM_XZ_OFF   SMEM_BF_BYTES
#define SMEM_TOTAL    (SMEM_XZ_OFF + 3 * 33 * 4)

// h in A-fragment order, fp16: [buf][ns2(8-col slice)][warp-row-group][lane]
// uint2 = { half2(h[R][c], h[R][c+1]), half2(h[R+8][c], h[R+8][c+1]) }
// with R = 16*wg + lane/4, c = 8*ns2 + 2*(lane%4)
__device__ uint2 g_hfrag[2][128][8][32];
__device__ float g_xz3[VV * 4 * HH];   // per-token x-side projection [v][gate*1024+j]
__device__ int   g_xidx[TT * BB];      // token index, time-major
__device__ int   g_x64;
// Data-flow progress flags. flag[ng] = s means: CTA ng has PUBLISHED h(s-1)
// (i.e. finished step s-2), and therefore has also finished READING h(s-2).
// Consumer of step t needs flag >= t+1 for every producer slice it touches.
// WAR safety: writer of h(t+1) (buffer (t+1)&1 == buffer of h(t-1)) has seen
// all flags >= t+1, which implies every CTA finished reading h(t-1).
__device__ unsigned g_flag[GRID];

// ---------------------------------------------------------------------------
__device__ __forceinline__ unsigned packh2(float a, float b) {
    __half2 h = __floats2half2_rn(a, b);
    return *(unsigned*)&h;
}

__device__ __forceinline__ uint2 ldcg2(const uint2* p) {
    uint2 r;
    asm volatile("ld.global.cg.v2.u32 {%0,%1},[%2];" : "=r"(r.x), "=r"(r.y) : "l"(p));
    return r;
}

__device__ __forceinline__ void mma_f16(float* c, unsigned a0, unsigned a1,
                                        unsigned a2, unsigned a3,
                                        unsigned b0, unsigned b1) {
    asm volatile(
        "mma.sync.aligned.m16n8k16.row.col.f32.f16.f16.f32 "
        "{%0,%1,%2,%3}, {%4,%5,%6,%7}, {%8,%9}, {%0,%1,%2,%3};"
        : "+f"(c[0]), "+f"(c[1]), "+f"(c[2]), "+f"(c[3])
        : "r"(a0), "r"(a1), "r"(a2), "r"(a3), "r"(b0), "r"(b1));
}

__device__ __forceinline__ float tanha(float x) {
    float y;
    asm("tanh.approx.f32 %0,%1;" : "=f"(y) : "f"(x));
    return y;
}

__device__ __forceinline__ float sigmf(float x) {
    float e = __expf(-x);
    float r;
    asm("rcp.approx.f32 %0,%1;" : "=f"(r) : "f"(1.0f + e));
    return r;
}

__device__ __forceinline__ float lstm_elem(float zg, float zi, float zf, float zo, float& c) {
    float gg = tanha(zg);
    float ii = sigmf(zi);
    float ff = sigmf(zf);
    float oo = sigmf(zo);
    c = c * ff + gg * ii;
    return tanha(c) * oo;
}

// Warp-collective: wait until producers [32g, 32g+32) have flag >= tgt.
__device__ __forceinline__ void wait_group(int g, unsigned tgt) {
    const unsigned* f = &g_flag[g * 32 + (threadIdx.x & 31)];
    unsigned v;
    do {
        asm volatile("ld.acquire.gpu.global.u32 %0,[%1];" : "=r"(v) : "l"(f));
    } while (__any_sync(0xffffffffu, v < tgt));
}

__device__ __forceinline__ void publish(int ng, unsigned val) {
    asm volatile("st.release.gpu.global.u32 [%0],%1;"
                 :: "l"(&g_flag[ng]), "r"(val) : "memory");
}

// ---------------------------------------------------------------------------
__global__ void k_init() {
    int tid = threadIdx.x;
    if (tid < GRID) g_flag[tid] = 0u;
}

// Detect x dtype without reading past an int32-sized allocation.
__global__ void k_detect(const unsigned* __restrict__ xw) {
    __shared__ int flag;
    if (threadIdx.x == 0) flag = 0;
    __syncthreads();
    for (int i = threadIdx.x; i < 2048; i += blockDim.x)
        if (xw[2 * i + 1] != 0u) flag = 1;
    __syncthreads();
    if (threadIdx.x == 0) g_x64 = (flag == 0) ? 1 : 0;
}

__global__ void k_idx(const void* __restrict__ x) {
    int b = blockIdx.x;
    int t = threadIdx.x;
    long long v;
    if (g_x64) v = ((const long long*)x)[(size_t)b * TT + t];
    else       v = ((const int*)x)[(size_t)b * TT + t];
    g_xidx[t * BB + b] = (int)v;
}

__global__ void k_xz3(const float* __restrict__ emb,
                      const float* __restrict__ W_gx, const float* __restrict__ W_ix,
                      const float* __restrict__ W_fx, const float* __restrict__ W_ox,
                      const float* __restrict__ b_g, const float* __restrict__ b_i,
                      const float* __restrict__ b_f, const float* __restrict__ b_o) {
    int gid = blockIdx.x * blockDim.x + threadIdx.x;
    if (gid >= VV * 4 * HH) return;
    int v = gid >> 12;
    int col = gid & 4095;
    int gate = col >> 10;
    int j = col & 1023;
    const float* W = (gate == 0) ? W_gx : (gate == 1) ? W_ix : (gate == 2) ? W_fx : W_ox;
    const float* bb = (gate == 0) ? b_g : (gate == 1) ? b_i : (gate == 2) ? b_f : b_o;
    float s = bb[j];
    const float* ev = emb + v * DD;
#pragma unroll 8
    for (int d = 0; d < DD; ++d) s += ev[d] * W[d * HH + j];
    g_xz3[gid] = s;
}

// ---------------------------------------------------------------------------
// Persistent recurrent kernel. CTA ng owns h-cols [8ng, 8ng+8).
// Warp wg: batch rows [16wg, 16wg+16), all 32 z-cols (ntile = gate).
// c-state in registers; z never leaves the mma accumulators.
// Synchronization is pure data-flow: per-producer flags, no global barrier.
__global__ void __launch_bounds__(NTHREADS, 1)
lstm_persistent(const float* __restrict__ W_gh, const float* __restrict__ W_ih,
                const float* __restrict__ W_fh, const float* __restrict__ W_oh) {
    extern __shared__ __align__(16) char smem[];
    uint4* Bf = (uint4*)smem;                     // [2][64][32]
    float* xzsm = (float*)(smem + SMEM_XZ_OFF);   // [3][33]

    const int ng = blockIdx.x;
    const int tid = threadIdx.x;
    const int wg = tid >> 5;
    const int lane = tid & 31;
    const int q = lane & 3;
    const int r4 = lane >> 2;
    const int R = 16 * wg + r4;

    // ---- One-time: weight slice -> fp16 B-fragments in SMEM ----
    for (int i = tid; i < 2 * KS16 * 32; i += NTHREADS) {
        int t = i & 31;
        int ks = (i >> 5) & 63;
        int p = i >> 11;                      // 0: gates g,i  1: gates f,o
        int col = ng * 8 + (t >> 2);
        int k0 = 16 * ks + 2 * (t & 3);
        const float* WA = p ? W_fh : W_gh;
        const float* WB = p ? W_oh : W_ih;
        uint4 v;
        v.x = packh2(WA[(size_t)k0 * HH + col],       WA[(size_t)(k0 + 1) * HH + col]);
        v.y = packh2(WA[(size_t)(k0 + 8) * HH + col], WA[(size_t)(k0 + 9) * HH + col]);
        v.z = packh2(WB[(size_t)k0 * HH + col],       WB[(size_t)(k0 + 1) * HH + col]);
        v.w = packh2(WB[(size_t)(k0 + 8) * HH + col], WB[(size_t)(k0 + 9) * HH + col]);
        Bf[i] = v;
    }

    // xz slice: xzsm[v][gate*8 + j] for this CTA's 8 cols
    for (int i = tid; i < VV * 32; i += NTHREADS) {
        int v = i >> 5;
        int lc = i & 31;
        xzsm[v * 33 + lc] = g_xz3[v * 4096 + (lc >> 3) * HH + ng * 8 + (lc & 7)];
    }

    // h(0) = 0 for our slice, then publish flag=1
    {
        uint2 z; z.x = 0u; z.y = 0u;
        g_hfrag[0][ng][wg][lane] = z;
    }
    __syncthreads();
    if (tid == 0) publish(ng, 1u);

    float c0 = 0.0f, c1 = 0.0f, c2 = 0.0f, c3 = 0.0f;

    for (int t = 0; t < TT; ++t) {
        const uint2* hb = &g_hfrag[t & 1][0][wg][lane];   // slice stride = 256 uint2
        const uint4* bf0 = Bf + lane;
        const uint4* bf1 = Bf + 2048 + lane;

        // Prefetch token indices for this step (hide L2 latency under k-loop)
        int vA = __ldg(&g_xidx[t * BB + R]);
        int vB = __ldg(&g_xidx[t * BB + R + 8]);

        float acc[4][4];
#pragma unroll
        for (int g = 0; g < 4; ++g)
#pragma unroll
            for (int e = 0; e < 4; ++e) acc[g][e] = 0.0f;

        // Consume k in 4 groups of 16 mma-chunks; wait only on that
        // group's 32 producers (data-flow pipeline, no global barrier).
#pragma unroll 1
        for (int grp = 0; grp < 4; ++grp) {
            wait_group(grp, (unsigned)(t + 1));
#pragma unroll 8
            for (int ks = 16 * grp; ks < 16 * grp + 16; ++ks) {
                uint2 A01 = ldcg2(hb + (2 * ks) * 256);
                uint2 A23 = ldcg2(hb + (2 * ks + 1) * 256);
                uint4 B01 = bf0[ks * 32];
                uint4 B23 = bf1[ks * 32];
                mma_f16(acc[0], A01.x, A01.y, A23.x, A23.y, B01.x, B01.y);
                mma_f16(acc[1], A01.x, A01.y, A23.x, A23.y, B01.z, B01.w);
                mma_f16(acc[2], A01.x, A01.y, A23.x, A23.y, B23.x, B23.y);
                mma_f16(acc[3], A01.x, A01.y, A23.x, A23.y, B23.z, B23.w);
            }
        }

        // Gate math entirely in registers (C-fragment == gate-math element set)
        const float* xA = xzsm + vA * 33 + 2 * q;
        const float* xB = xzsm + vB * 33 + 2 * q;

        float h0 = lstm_elem(acc[0][0] + xA[0], acc[1][0] + xA[8],
                             acc[2][0] + xA[16], acc[3][0] + xA[24], c0);
        float h1 = lstm_elem(acc[0][1] + xA[1], acc[1][1] + xA[9],
                             acc[2][1] + xA[17], acc[3][1] + xA[25], c1);
        float h2 = lstm_elem(acc[0][2] + xB[0], acc[1][2] + xB[8],
                             acc[2][2] + xB[16], acc[3][2] + xB[24], c2);
        float h3 = lstm_elem(acc[0][3] + xB[1], acc[1][3] + xB[9],
                             acc[2][3] + xB[17], acc[3][3] + xB[25], c3);

        uint2 out;
        out.x = packh2(h0, h1);
        out.y = packh2(h2, h3);
        g_hfrag[(t + 1) & 1][ng][wg][lane] = out;

        // Publish h(t+1): all CTA stores ordered before the release store.
        __syncthreads();
        if (tid == 0) publish(ng, (unsigned)(t + 2));
    }
}

// ---------------------------------------------------------------------------
// Final projection + log_softmax; decodes fragment layout. h_final in buf 0.
__global__ void k_final(const float* __restrict__ W_ph, const float* __restrict__ b_p,
                        float* __restrict__ out) {
    __shared__ float part[CC][128];
    __shared__ float lg[CC];
    __shared__ float red[2];
    int b = blockIdx.x;
    int tid = threadIdx.x;
    int wg = b >> 4;
    int rr = b & 7;
    int e1 = (b >> 3) & 1;

    float loc[CC];
#pragma unroll
    for (int c = 0; c < CC; ++c) loc[c] = 0.0f;
    for (int col = tid; col < HH; col += 128) {
        int ns2 = col >> 3;
        int q = (col & 7) >> 1;
        int e0 = col & 1;
        uint2 ent = g_hfrag[0][ns2][wg][rr * 4 + q];
        unsigned word = e1 ? ent.y : ent.x;
        __half2 hh = *(__half2*)&word;
        float hv = e0 ? __high2float(hh) : __low2float(hh);
#pragma unroll
        for (int c = 0; c < CC; ++c) loc[c] += hv * W_ph[col * CC + c];
    }
#pragma unroll
    for (int c = 0; c < CC; ++c) part[c][tid] = loc[c];
    __syncthreads();
    if (tid < CC) {
        float s = 0.0f;
        for (int k = 0; k < 128; ++k) s += part[tid][k];
        lg[tid] = s + b_p[tid];
    }
    __syncthreads();
    if (tid == 0) {
        float m = -1e30f;
        for (int c = 0; c < CC; ++c) m = fmaxf(m, lg[c]);
        float s = 0.0f;
        for (int c = 0; c < CC; ++c) s += expf(lg[c] - m);
        red[0] = m;
        red[1] = logf(s);
    }
    __syncthreads();
    if (tid < CC) out[b * CC + tid] = lg[tid] - red[0] - red[1];
}

// ---------------------------------------------------------------------------
extern "C" void kernel_launch(void* const* d_in, const int* in_sizes, int n_in,
                              void* d_out, int out_size) {
    const void* x        = d_in[0];
    const float* emb     = (const float*)d_in[1];
    const float* W_gx    = (const float*)d_in[2];
    const float* W_ix    = (const float*)d_in[3];
    const float* W_fx    = (const float*)d_in[4];
    const float* W_ox    = (const float*)d_in[5];
    const float* W_gh    = (const float*)d_in[6];
    const float* W_ih    = (const float*)d_in[7];
    const float* W_fh    = (const float*)d_in[8];
    const float* W_oh    = (const float*)d_in[9];
    const float* b_g     = (const float*)d_in[10];
    const float* b_i     = (const float*)d_in[11];
    const float* b_f     = (const float*)d_in[12];
    const float* b_o     = (const float*)d_in[13];
    const float* W_ph    = (const float*)d_in[14];
    const float* b_p     = (const float*)d_in[15];
    float* out = (float*)d_out;

    cudaFuncSetAttribute(lstm_persistent, cudaFuncAttributeMaxDynamicSharedMemorySize,
                         SMEM_TOTAL);

    k_init<<<1, 128>>>();
    k_detect<<<1, 256>>>((const unsigned*)x);
    k_idx<<<BB, TT>>>(x);
    k_xz3<<<(VV * 4 * HH + 255) / 256, 256>>>(emb, W_gx, W_ix, W_fx, W_ox, b_g, b_i, b_f, b_o);
    lstm_persistent<<<GRID, NTHREADS, SMEM_TOTAL>>>(W_gh, W_ih, W_fh, W_oh);
    k_final<<<BB, 128>>>(W_ph, b_p, out);
}